// round 14
// baseline (speedup 1.0000x reference)
#include <cuda_runtime.h>
#include <cuda_bf16.h>
#include <math.h>
#include <float.h>
#include <stdint.h>

#define BATCH 2
#define NPTS  1000
#define KNN   8
#define NPAIR ((NPTS*(NPTS-1))/2)   // 499500

// ---------------------------------------------------------------------------
// Static scratch
// ---------------------------------------------------------------------------
__device__ int   g_knn [BATCH*NPTS*KNN];
__device__ float g_d2  [BATCH*NPTS*NPTS];      // 8 MB distance matrix
__device__ float g_A   [BATCH*NPTS*256];       // c2a AB / hh [2000][256]
__device__ float g_H   [BATCH*NPTS*KNN*256];   // stage-2 edge hidden / sm hidden
__device__ float g_T   [BATCH*NPTS*512];       // c3a AB [2000][512]
__device__ float g_x1  [BATCH*NPTS*32];
__device__ float g_x2  [BATCH*NPTS*128];
__device__ float g_xcat[BATCH*NPTS*672];
__device__ float g_sf  [BATCH*NPTS*128];
__device__ float g_hg  [BATCH*128];
// bf16 split-concat buffers
__device__ __nv_bfloat16 g_Acat [16000*768];   // c3b activations / sm1 activations (2000x2016)
__device__ __nv_bfloat16 g_Wcat [512*768];     // c3b weights
__device__ __nv_bfloat16 g_Wcat2[256*2016];    // sm1 weights
// ---------------------------------------------------------------------------
// cp.async helpers
// ---------------------------------------------------------------------------
__device__ __forceinline__ void cp_async16(void* smem_ptr, const void* gmem_ptr) {
    unsigned dst = (unsigned)__cvta_generic_to_shared(smem_ptr);
    asm volatile("cp.async.cg.shared.global [%0], [%1], 16;\n" :: "r"(dst), "l"(gmem_ptr));
}
__device__ __forceinline__ void cp_commit() { asm volatile("cp.async.commit_group;\n" ::: "memory"); }
__device__ __forceinline__ void cp_wait0()  { asm volatile("cp.async.wait_group 0;\n" ::: "memory"); }

// ---------------------------------------------------------------------------
// Pairwise distance with inline row-norms (64x64, 4x4 micro — R11-proven)
// ---------------------------------------------------------------------------
template<int C>
__global__ void __launch_bounds__(256)
dist_kernel(const float* __restrict__ x, float* __restrict__ d2)
{
    const int b  = blockIdx.z;
    const int n0 = blockIdx.y * 64;
    const int m0 = blockIdx.x * 64;
    const float* xb = x + (size_t)b * NPTS * C;

    __shared__ float As[32][68];
    __shared__ float Bs[32][68];

    const int tid = threadIdx.x;
    const int ti = tid >> 4;
    const int tj = tid & 15;

    float acc[4][4];
    float sqa[4], sqbv[4];
    #pragma unroll
    for (int i = 0; i < 4; i++) { sqa[i] = 0.f; sqbv[i] = 0.f; }
    #pragma unroll
    for (int i = 0; i < 4; i++)
        #pragma unroll
        for (int j = 0; j < 4; j++) acc[i][j] = 0.f;

    for (int k0 = 0; k0 < C; k0 += 32) {
        #pragma unroll
        for (int v = tid; v < 512; v += 256) {
            int r  = v >> 3;
            int cq = (v & 7) * 4;
            {
                int row = n0 + r;
                float4 a4 = make_float4(0.f, 0.f, 0.f, 0.f);
                if (row < NPTS) {
                    if ((C & 31) == 0) {
                        a4 = *reinterpret_cast<const float4*>(&xb[(size_t)row*C + k0 + cq]);
                    } else {
                        float tmp[4];
                        #pragma unroll
                        for (int t2 = 0; t2 < 4; t2++) {
                            int k = k0 + cq + t2;
                            tmp[t2] = (k < C) ? xb[(size_t)row*C + k] : 0.f;
                        }
                        a4 = make_float4(tmp[0], tmp[1], tmp[2], tmp[3]);
                    }
                }
                As[cq+0][r] = a4.x; As[cq+1][r] = a4.y;
                As[cq+2][r] = a4.z; As[cq+3][r] = a4.w;
            }
            {
                int row = m0 + r;
                float4 b4 = make_float4(0.f, 0.f, 0.f, 0.f);
                if (row < NPTS) {
                    if ((C & 31) == 0) {
                        b4 = *reinterpret_cast<const float4*>(&xb[(size_t)row*C + k0 + cq]);
                    } else {
                        float tmp[4];
                        #pragma unroll
                        for (int t2 = 0; t2 < 4; t2++) {
                            int k = k0 + cq + t2;
                            tmp[t2] = (k < C) ? xb[(size_t)row*C + k] : 0.f;
                        }
                        b4 = make_float4(tmp[0], tmp[1], tmp[2], tmp[3]);
                    }
                }
                Bs[cq+0][r] = b4.x; Bs[cq+1][r] = b4.y;
                Bs[cq+2][r] = b4.z; Bs[cq+3][r] = b4.w;
            }
        }
        __syncthreads();
        #pragma unroll
        for (int kk = 0; kk < 32; kk++) {
            float ra[4], rb[4];
            *reinterpret_cast<float4*>(ra) = *reinterpret_cast<const float4*>(&As[kk][ti*4]);
            *reinterpret_cast<float4*>(rb) = *reinterpret_cast<const float4*>(&Bs[kk][tj*4]);
            #pragma unroll
            for (int i = 0; i < 4; i++) sqa[i]  = fmaf(ra[i], ra[i], sqa[i]);
            #pragma unroll
            for (int j = 0; j < 4; j++) sqbv[j] = fmaf(rb[j], rb[j], sqbv[j]);
            #pragma unroll
            for (int i = 0; i < 4; i++)
                #pragma unroll
                for (int j = 0; j < 4; j++)
                    acc[i][j] = fmaf(ra[i], rb[j], acc[i][j]);
        }
        __syncthreads();
    }

    const int ni = n0 + ti*4;
    const int mj = m0 + tj*4;
    #pragma unroll
    for (int i = 0; i < 4; i++) {
        if (ni+i >= NPTS) continue;
        #pragma unroll
        for (int j = 0; j < 4; j++) {
            if (mj+j >= NPTS) continue;
            d2[((size_t)b*NPTS + ni+i)*NPTS + mj+j] = sqa[i] + sqbv[j] - 2.f*acc[i][j];
        }
    }
}

// ---------------------------------------------------------------------------
// Top-8 per row (ties -> lower idx) — block/smem version (proven)
// ---------------------------------------------------------------------------
__global__ void topk_kernel(const float* __restrict__ d2, int* __restrict__ knn)
{
    const int b = blockIdx.y;
    const int n = blockIdx.x;
    const int tid = threadIdx.x;   // 128
    const float* row = d2 + ((size_t)b*NPTS + n)*NPTS;

    __shared__ float sd[128*8];
    __shared__ int   si[128*8];

    float bd[8]; int bi[8];
    #pragma unroll
    for (int k = 0; k < 8; k++) { bd[k] = FLT_MAX; bi[k] = 0x7FFFFFFF; }

    for (int m = tid; m < NPTS; m += 128) {
        float d = row[m];
        if (d < bd[7] || (d == bd[7] && m < bi[7])) {
            int p = 7;
            #pragma unroll
            for (int it = 0; it < 7; it++) {
                if (p > 0 && (d < bd[p-1] || (d == bd[p-1] && m < bi[p-1]))) {
                    bd[p] = bd[p-1]; bi[p] = bi[p-1]; p--;
                }
            }
            bd[p] = d; bi[p] = m;
        }
    }
    #pragma unroll
    for (int k = 0; k < 8; k++) { sd[tid*8+k] = bd[k]; si[tid*8+k] = bi[k]; }

    for (int s = 64; s >= 1; s >>= 1) {
        __syncthreads();
        if (tid < s) {
            float* Ad = &sd[tid*8];        int* Ai = &si[tid*8];
            float* Bd = &sd[(tid+s)*8];    int* Bi = &si[(tid+s)*8];
            float od[8]; int oi[8];
            int a = 0, c2 = 0;
            #pragma unroll
            for (int o = 0; o < 8; o++) {
                bool ta = (Ad[a] < Bd[c2]) || (Ad[a] == Bd[c2] && Ai[a] < Bi[c2]);
                if (ta) { od[o] = Ad[a]; oi[o] = Ai[a]; a++; }
                else    { od[o] = Bd[c2]; oi[o] = Bi[c2]; c2++; }
            }
            #pragma unroll
            for (int o = 0; o < 8; o++) { Ad[o] = od[o]; Ai[o] = oi[o]; }
        }
    }
    __syncthreads();
    if (tid < 8) knn[((size_t)b*NPTS + n)*8 + tid] = si[tid];
}

// ---------------------------------------------------------------------------
// Fully fused EdgeConv1 (one warp per point) with neighbor prefetch
// ---------------------------------------------------------------------------
__global__ void __launch_bounds__(256)
ec1_fused_kernel(const float* __restrict__ pos, const int* __restrict__ knn,
                 const float* __restrict__ W1, const float* __restrict__ b1,
                 const float* __restrict__ W2, const float* __restrict__ b2,
                 float* __restrict__ x1, float* __restrict__ xcat)
{
    __shared__ float sW1[96], sb1[16], sW2[512], sb2[32];
    const int tid = threadIdx.x;
    if (tid < 96) sW1[tid] = W1[tid];
    if (tid < 16) sb1[tid] = b1[tid];
    if (tid < 32) sb2[tid] = b2[tid];
    for (int t = tid; t < 512; t += 256) sW2[t] = W2[t];
    __syncthreads();

    const int warp = tid >> 5, lane = tid & 31;
    const int p = blockIdx.x * 8 + warp;
    if (p >= BATCH*NPTS) return;
    const int b = p / NPTS;

    const float* xi = pos + (size_t)p*3;
    const float xi0 = xi[0], xi1 = xi[1], xi2 = xi[2];

    // prefetch all neighbor indices + coordinates (batched loads)
    int js[8];
    #pragma unroll
    for (int e = 0; e < 8; e++) js[e] = knn[p*8 + e];
    float xjv[8][3];
    #pragma unroll
    for (int e = 0; e < 8; e++) {
        const float* xj = pos + ((size_t)b*NPTS + js[e])*3;
        xjv[e][0] = xj[0]; xjv[e][1] = xj[1]; xjv[e][2] = xj[2];
    }

    float best = -FLT_MAX;
    #pragma unroll
    for (int e = 0; e < 8; e++) {
        float d0 = xjv[e][0]-xi0, d1 = xjv[e][1]-xi1, d2v = xjv[e][2]-xi2;
        float macc = 0.f;
        #pragma unroll
        for (int k = 0; k < 16; k++) {
            float h = sb1[k];
            h = fmaf(xi0, sW1[0*16+k], h);
            h = fmaf(d0,  sW1[3*16+k], h);
            h = fmaf(xi1, sW1[1*16+k], h);
            h = fmaf(d1,  sW1[4*16+k], h);
            h = fmaf(xi2, sW1[2*16+k], h);
            h = fmaf(d2v, sW1[5*16+k], h);
            h = fmaxf(h, 0.f);
            macc = fmaf(h, sW2[k*32 + lane], macc);
        }
        best = fmaxf(best, macc + sb2[lane]);
    }
    x1[(size_t)p*32 + lane] = best;
    xcat[(size_t)p*672 + lane] = best;
}

// ---------------------------------------------------------------------------
// SGEMM64 with register-prefetch pipeline (row-major A). K%16==0, N%64==0.
// ---------------------------------------------------------------------------
__global__ void __launch_bounds__(256)
sgemm64_kernel(const float* __restrict__ A, const float* __restrict__ W,
               const float* __restrict__ bias, float* __restrict__ C,
               int M, int N, int K, int relu)
{
    __shared__ float As[16][64];
    __shared__ float Bs[16][64];

    const int tid = threadIdx.x;
    const int tx = tid & 15;
    const int ty = tid >> 4;
    const int row0 = blockIdx.y * 64;
    const int col0 = blockIdx.x * 64;

    const int lm  = tid >> 2;
    const int lkq = (tid & 3) * 4;
    const int lkk = tid >> 4;
    const int ln4 = (tid & 15) * 4;

    float acc[4][4];
    #pragma unroll
    for (int i = 0; i < 4; i++)
        #pragma unroll
        for (int j = 0; j < 4; j++) acc[i][j] = 0.f;

    auto loadA = [&](int k0) -> float4 {
        int gm = min(row0 + lm, M - 1);
        return *reinterpret_cast<const float4*>(&A[(size_t)gm * K + k0 + lkq]);
    };
    auto loadB = [&](int k0) -> float4 {
        return *reinterpret_cast<const float4*>(&W[(size_t)(k0 + lkk) * N + col0 + ln4]);
    };

    float4 ra4 = loadA(0);
    float4 rb4 = loadB(0);

    for (int k0 = 0; k0 < K; k0 += 16) {
        As[lkq+0][lm] = ra4.x; As[lkq+1][lm] = ra4.y;
        As[lkq+2][lm] = ra4.z; As[lkq+3][lm] = ra4.w;
        *reinterpret_cast<float4*>(&Bs[lkk][ln4]) = rb4;
        __syncthreads();
        if (k0 + 16 < K) { ra4 = loadA(k0 + 16); rb4 = loadB(k0 + 16); }
        #pragma unroll
        for (int kk = 0; kk < 16; kk++) {
            float ra[4], rb[4];
            *reinterpret_cast<float4*>(ra) = *reinterpret_cast<const float4*>(&As[kk][ty*4]);
            *reinterpret_cast<float4*>(rb) = *reinterpret_cast<const float4*>(&Bs[kk][tx*4]);
            #pragma unroll
            for (int i = 0; i < 4; i++)
                #pragma unroll
                for (int j = 0; j < 4; j++)
                    acc[i][j] = fmaf(ra[i], rb[j], acc[i][j]);
        }
        __syncthreads();
    }
    #pragma unroll
    for (int i = 0; i < 4; i++) {
        int gm = row0 + ty*4 + i;
        if (gm >= M) continue;
        #pragma unroll
        for (int j = 0; j < 4; j++) {
            int gn = col0 + tx*4 + j;
            float v = acc[i][j];
            if (bias) v += bias[gn];
            if (relu) v = fmaxf(v, 0.f);
            C[(size_t)gm * N + gn] = v;
        }
    }
}

// ---------------------------------------------------------------------------
// Dual-weight SGEMM64 with register-prefetch pipeline (c2a / c3a / hh)
// ---------------------------------------------------------------------------
__global__ void __launch_bounds__(256)
sgemm64_dual_kernel(const float* __restrict__ A,
                    const float* __restrict__ Wa, const float* __restrict__ Wb,
                    const float* __restrict__ bias,
                    float* __restrict__ C,
                    int M, int Nw, int K)
{
    __shared__ float As[16][64];
    __shared__ float Bs[16][64];

    const int tid = threadIdx.x;
    const int tx = tid & 15;
    const int ty = tid >> 4;
    const int row0 = blockIdx.y * 64;
    const int col0 = blockIdx.x * 64;
    const int Ntot = 2 * Nw;
    const float* W = (col0 < Nw) ? Wa : Wb;
    const int colw0 = (col0 < Nw) ? col0 : col0 - Nw;

    const int lm  = tid >> 2;
    const int lkq = (tid & 3) * 4;
    const int lkk = tid >> 4;
    const int ln4 = (tid & 15) * 4;

    float acc[4][4];
    #pragma unroll
    for (int i = 0; i < 4; i++)
        #pragma unroll
        for (int j = 0; j < 4; j++) acc[i][j] = 0.f;

    auto loadA = [&](int k0) -> float4 {
        int gm = min(row0 + lm, M - 1);
        return *reinterpret_cast<const float4*>(&A[(size_t)gm * K + k0 + lkq]);
    };
    auto loadB = [&](int k0) -> float4 {
        return *reinterpret_cast<const float4*>(&W[(size_t)(k0 + lkk) * Nw + colw0 + ln4]);
    };

    float4 ra4 = loadA(0);
    float4 rb4 = loadB(0);

    for (int k0 = 0; k0 < K; k0 += 16) {
        As[lkq+0][lm] = ra4.x; As[lkq+1][lm] = ra4.y;
        As[lkq+2][lm] = ra4.z; As[lkq+3][lm] = ra4.w;
        *reinterpret_cast<float4*>(&Bs[lkk][ln4]) = rb4;
        __syncthreads();
        if (k0 + 16 < K) { ra4 = loadA(k0 + 16); rb4 = loadB(k0 + 16); }
        #pragma unroll
        for (int kk = 0; kk < 16; kk++) {
            float ra[4], rb[4];
            *reinterpret_cast<float4*>(ra) = *reinterpret_cast<const float4*>(&As[kk][ty*4]);
            *reinterpret_cast<float4*>(rb) = *reinterpret_cast<const float4*>(&Bs[kk][tx*4]);
            #pragma unroll
            for (int i = 0; i < 4; i++)
                #pragma unroll
                for (int j = 0; j < 4; j++)
                    acc[i][j] = fmaf(ra[i], rb[j], acc[i][j]);
        }
        __syncthreads();
    }
    #pragma unroll
    for (int i = 0; i < 4; i++) {
        int gm = row0 + ty*4 + i;
        if (gm >= M) continue;
        #pragma unroll
        for (int j = 0; j < 4; j++) {
            int gn = col0 + tx*4 + j;
            float v = acc[i][j];
            if (bias) v += bias[gn];
            C[(size_t)gm * Ntot + gn] = v;
        }
    }
}

// ---------------------------------------------------------------------------
// c2b SGEMM128 with fused neighbor-max epilogue (M=16000, N=128, K=64)
// ---------------------------------------------------------------------------
__global__ void __launch_bounds__(256, 2)
c2b_fused_kernel(const float* __restrict__ A, const float* __restrict__ W,
                 const float* __restrict__ bias,
                 float* __restrict__ x2, float* __restrict__ xcat)
{
    const int BK = 16, N = 128, K = 64;
    __shared__ float As[BK][128];
    __shared__ float Bs[BK][128];

    const int tid = threadIdx.x;
    const int tx = tid & 15;
    const int ty = tid >> 4;
    const int row0 = blockIdx.y * 128;

    float acc[8][8];
    #pragma unroll
    for (int i = 0; i < 8; i++)
        #pragma unroll
        for (int j = 0; j < 8; j++) acc[i][j] = 0.f;

    for (int k0 = 0; k0 < K; k0 += BK) {
        #pragma unroll
        for (int t = 0; t < 2; t++) {
            int v  = tid + t * 256;
            int m  = v >> 2;
            int kq = (v & 3) * 4;
            float4 a4 = *reinterpret_cast<const float4*>(&A[(size_t)(row0 + m) * K + k0 + kq]);
            As[kq+0][m] = a4.x; As[kq+1][m] = a4.y;
            As[kq+2][m] = a4.z; As[kq+3][m] = a4.w;
        }
        #pragma unroll
        for (int t = 0; t < 2; t++) {
            int v  = tid + t * 256;
            int n4 = (v & 31) * 4;
            int kk = v >> 5;
            float4 b4 = *reinterpret_cast<const float4*>(&W[(size_t)(k0 + kk) * N + n4]);
            *reinterpret_cast<float4*>(&Bs[kk][n4]) = b4;
        }
        __syncthreads();
        #pragma unroll
        for (int kk = 0; kk < BK; kk++) {
            float ra[8], rb[8];
            *reinterpret_cast<float4*>(&ra[0]) = *reinterpret_cast<const float4*>(&As[kk][ty*8]);
            *reinterpret_cast<float4*>(&ra[4]) = *reinterpret_cast<const float4*>(&As[kk][ty*8+4]);
            *reinterpret_cast<float4*>(&rb[0]) = *reinterpret_cast<const float4*>(&Bs[kk][tx*8]);
            *reinterpret_cast<float4*>(&rb[4]) = *reinterpret_cast<const float4*>(&Bs[kk][tx*8+4]);
            #pragma unroll
            for (int i = 0; i < 8; i++)
                #pragma unroll
                for (int j = 0; j < 8; j++)
                    acc[i][j] = fmaf(ra[i], rb[j], acc[i][j]);
        }
        __syncthreads();
    }

    const int p = (row0 + ty*8) >> 3;
    float mx[8];
    #pragma unroll
    for (int j = 0; j < 8; j++) {
        float v = acc[0][j];
        #pragma unroll
        for (int i = 1; i < 8; i++) v = fmaxf(v, acc[i][j]);
        mx[j] = v + bias[tx*8 + j];
    }
    *reinterpret_cast<float4*>(&x2[(size_t)p*128 + tx*8])     = *reinterpret_cast<float4*>(&mx[0]);
    *reinterpret_cast<float4*>(&x2[(size_t)p*128 + tx*8 + 4]) = *reinterpret_cast<float4*>(&mx[4]);
    *reinterpret_cast<float4*>(&xcat[(size_t)p*672 + 32 + tx*8])     = *reinterpret_cast<float4*>(&mx[0]);
    *reinterpret_cast<float4*>(&xcat[(size_t)p*672 + 32 + tx*8 + 4]) = *reinterpret_cast<float4*>(&mx[4]);
}

// ---------------------------------------------------------------------------
// Stage-2 edge combine (fp32 H output)
// ---------------------------------------------------------------------------
__global__ void edge_combine_kernel(const float* __restrict__ A,
                                    const float* __restrict__ Bv,
                                    int lda4,
                                    const int* __restrict__ knn,
                                    const float* __restrict__ b1,
                                    float* __restrict__ H, int Nh4)
{
    int t = blockIdx.x * blockDim.x + threadIdx.x;
    int all = BATCH*NPTS*KNN*Nh4;
    if (t >= all) return;
    int c4 = t % Nh4;
    int e  = t / Nh4;
    int n  = (e / KNN) % NPTS;
    int b  = e / (KNN*NPTS);
    int j  = knn[e];
    size_t pi = (size_t)b*NPTS + n;
    size_t pj = (size_t)b*NPTS + j;
    float4 a  = reinterpret_cast<const float4*>(A)[pi*lda4 + c4];
    float4 bi = reinterpret_cast<const float4*>(Bv)[pi*lda4 + c4];
    float4 bj = reinterpret_cast<const float4*>(Bv)[pj*lda4 + c4];
    float4 bb = reinterpret_cast<const float4*>(b1)[c4];
    float4 h;
    h.x = fmaxf(a.x + bj.x - bi.x + bb.x, 0.f);
    h.y = fmaxf(a.y + bj.y - bi.y + bb.y, 0.f);
    h.z = fmaxf(a.z + bj.z - bi.z + bb.z, 0.f);
    h.w = fmaxf(a.w + bj.w - bi.w + bb.w, 0.f);
    reinterpret_cast<float4*>(H)[(size_t)e*Nh4 + c4] = h;
}

// ---------------------------------------------------------------------------
// Stage-3 edge combine + bf16 split -> Acat[e][768] = [hi|hi|lo]
// ---------------------------------------------------------------------------
__global__ void edge_combine_split_kernel(const float* __restrict__ A,
                                          const float* __restrict__ Bv,
                                          int lda4,
                                          const int* __restrict__ knn,
                                          const float* __restrict__ b1,
                                          __nv_bfloat16* __restrict__ Acat)
{
    int t = blockIdx.x * blockDim.x + threadIdx.x;
    int all = BATCH*NPTS*KNN*64;
    if (t >= all) return;
    int c4 = t & 63;
    int e  = t >> 6;
    int n  = (e / KNN) % NPTS;
    int b  = e / (KNN*NPTS);
    int j  = knn[e];
    size_t pi = (size_t)b*NPTS + n;
    size_t pj = (size_t)b*NPTS + j;
    float4 a  = reinterpret_cast<const float4*>(A)[pi*lda4 + c4];
    float4 bi = reinterpret_cast<const float4*>(Bv)[pi*lda4 + c4];
    float4 bj = reinterpret_cast<const float4*>(Bv)[pj*lda4 + c4];
    float4 bb = reinterpret_cast<const float4*>(b1)[c4];
    float h0 = fmaxf(a.x + bj.x - bi.x + bb.x, 0.f);
    float h1 = fmaxf(a.y + bj.y - bi.y + bb.y, 0.f);
    float h2 = fmaxf(a.z + bj.z - bi.z + bb.z, 0.f);
    float h3 = fmaxf(a.w + bj.w - bi.w + bb.w, 0.f);

    __nv_bfloat16 H0 = __float2bfloat16(h0), H1 = __float2bfloat16(h1);
    __nv_bfloat16 H2 = __float2bfloat16(h2), H3 = __float2bfloat16(h3);
    __nv_bfloat16 L0 = __float2bfloat16(h0 - __bfloat162float(H0));
    __nv_bfloat16 L1 = __float2bfloat16(h1 - __bfloat162float(H1));
    __nv_bfloat16 L2 = __float2bfloat16(h2 - __bfloat162float(H2));
    __nv_bfloat16 L3 = __float2bfloat16(h3 - __bfloat162float(H3));

    size_t base = (size_t)e * 768 + c4*4;
    __nv_bfloat162* p0 = reinterpret_cast<__nv_bfloat162*>(&Acat[base]);
    __nv_bfloat162* p1 = reinterpret_cast<__nv_bfloat162*>(&Acat[base + 256]);
    __nv_bfloat162* p2 = reinterpret_cast<__nv_bfloat162*>(&Acat[base + 512]);
    __nv_bfloat162 hiA; hiA.x = H0; hiA.y = H1;
    __nv_bfloat162 hiB; hiB.x = H2; hiB.y = H3;
    __nv_bfloat162 loA; loA.x = L0; loA.y = L1;
    __nv_bfloat162 loB; loB.x = L2; loB.y = L3;
    p0[0] = hiA; p0[1] = hiB;
    p1[0] = hiA; p1[1] = hiB;
    p2[0] = loA; p2[1] = loB;
}

// ---------------------------------------------------------------------------
// Generic splits (R8-proven): A [M][K] -> [M][3K] = [hi|hi|lo]
// ---------------------------------------------------------------------------
__global__ void split_a3_g(const float* __restrict__ in, __nv_bfloat16* __restrict__ out,
                           int total, int K)
{
    int t = blockIdx.x * 256 + threadIdx.x;
    if (t >= total) return;
    int row = t / K, k = t - row * K;
    float v = in[t];
    __nv_bfloat16 h = __float2bfloat16(v);
    __nv_bfloat16 l = __float2bfloat16(v - __bfloat162float(h));
    size_t base = (size_t)row * (3*K);
    out[base + k]       = h;
    out[base + K + k]   = h;
    out[base + 2*K + k] = l;
}

// W [K][N] -> out [N][3K] = [hi|lo|hi]
__global__ void split_w3_g(const float* __restrict__ W, __nv_bfloat16* __restrict__ out,
                           int K, int N)
{
    __shared__ float tile[32][33];
    int n0 = blockIdx.x * 32, k0 = blockIdx.y * 32;
    int tx = threadIdx.x & 31, ty = threadIdx.x >> 5;
    for (int r = ty; r < 32; r += 8)
        tile[r][tx] = (k0 + r < K && n0 + tx < N) ? W[(size_t)(k0+r)*N + n0 + tx] : 0.f;
    __syncthreads();
    for (int r = ty; r < 32; r += 8) {
        int n = n0 + r, k = k0 + tx;
        if (n >= N || k >= K) continue;
        float v = tile[tx][r];
        __nv_bfloat16 h = __float2bfloat16(v);
        __nv_bfloat16 l = __float2bfloat16(v - __bfloat162float(h));
        size_t base = (size_t)n * (3*K);
        out[base + k]       = h;
        out[base + K + k]   = l;
        out[base + 2*K + k] = h;
    }
}

// ---------------------------------------------------------------------------
// c3b weight split (dedicated 768 layout)
// ---------------------------------------------------------------------------
__global__ void split_w3_kernel(const float* __restrict__ W,
                                __nv_bfloat16* __restrict__ Bcat)
{
    __shared__ float tile[32][33];
    int n0 = blockIdx.x * 32, k0 = blockIdx.y * 32;
    int tx = threadIdx.x & 31, ty = threadIdx.x >> 5;
    for (int r = ty; r < 32; r += 8) tile[r][tx] = W[(size_t)(k0+r)*512 + n0 + tx];
    __syncthreads();
    for (int r = ty; r < 32; r += 8) {
        float v = tile[tx][r];
        int n = n0 + r, k = k0 + tx;
        __nv_bfloat16 h = __float2bfloat16(v);
        __nv_bfloat16 l = __float2bfloat16(v - __bfloat162float(h));
        size_t base = (size_t)n * 768;
        Bcat[base + k]       = h;
        Bcat[base + 256 + k] = l;
        Bcat[base + 512 + k] = h;
    }
}

// ---------------------------------------------------------------------------
// Generic HMMA bf16 GEMM (R8-proven): C = act(Acat @ Bcat^T + bias)
// CTA 128x128, BK=32, 8 warps, M-guarded. Kt%32==0, N%128==0.
// ---------------------------------------------------------------------------
__global__ void __launch_bounds__(256, 2)
mma_g_kernel(const __nv_bfloat16* __restrict__ Acat,
             const __nv_bfloat16* __restrict__ Bcat,
             const float* __restrict__ bias,
             float* __restrict__ C,
             int M, int N, int Kt, int relu)
{
    __shared__ __nv_bfloat16 sA[2][128][40];
    __shared__ __nv_bfloat16 sB[2][128][40];

    const int tid  = threadIdx.x;
    const int wid  = tid >> 5;
    const int lane = tid & 31;
    const int m0 = blockIdx.x * 128;
    const int n0 = blockIdx.y * 128;
    const int wr = wid >> 2;
    const int wc = wid & 3;

    float acc[4][4][4];
    #pragma unroll
    for (int a = 0; a < 4; a++)
        #pragma unroll
        for (int b = 0; b < 4; b++)
            #pragma unroll
            for (int c = 0; c < 4; c++) acc[a][b][c] = 0.f;

    auto load_tile = [&](int buf, int k0) {
        #pragma unroll
        for (int t2 = 0; t2 < 2; t2++) {
            int c   = tid + t2 * 256;
            int row = c >> 2;
            int k8  = (c & 3) * 8;
            int gm  = min(m0 + row, M - 1);
            cp_async16(&sA[buf][row][k8], Acat + (size_t)gm*Kt + k0 + k8);
            cp_async16(&sB[buf][row][k8], Bcat + (size_t)(n0 + row)*Kt + k0 + k8);
        }
    };

    load_tile(0, 0);
    cp_commit();
    int buf = 0;
    for (int k0 = 0; k0 < Kt; k0 += 32) {
        cp_wait0();
        __syncthreads();
        if (k0 + 32 < Kt) { load_tile(buf ^ 1, k0 + 32); cp_commit(); }

        #pragma unroll
        for (int ks = 0; ks < 2; ks++) {
            const int kb = ks * 16;
            uint32_t af[4][4], bf[4][2];
            #pragma unroll
            for (int ma = 0; ma < 4; ma++) {
                int m = wr*64 + ma*16 + (lane & 15);
                int k = kb + ((lane >> 4) << 3);
                uint32_t addr = (uint32_t)__cvta_generic_to_shared(&sA[buf][m][k]);
                asm volatile("ldmatrix.sync.aligned.m8n8.x4.shared.b16 {%0,%1,%2,%3}, [%4];"
                    : "=r"(af[ma][0]), "=r"(af[ma][1]), "=r"(af[ma][2]), "=r"(af[ma][3])
                    : "r"(addr));
            }
            #pragma unroll
            for (int na = 0; na < 4; na++) {
                int n = wc*32 + na*8 + (lane & 7);
                int k = kb + (lane & 8);
                uint32_t addr = (uint32_t)__cvta_generic_to_shared(&sB[buf][n][k]);
                asm volatile("ldmatrix.sync.aligned.m8n8.x2.shared.b16 {%0,%1}, [%2];"
                    : "=r"(bf[na][0]), "=r"(bf[na][1])
                    : "r"(addr));
            }
            #pragma unroll
            for (int ma = 0; ma < 4; ma++)
                #pragma unroll
                for (int na = 0; na < 4; na++)
                    asm volatile(
                        "mma.sync.aligned.m16n8k16.row.col.f32.bf16.bf16.f32 "
                        "{%0,%1,%2,%3}, {%4,%5,%6,%7}, {%8,%9}, {%0,%1,%2,%3};"
                        : "+f"(acc[ma][na][0]), "+f"(acc[ma][na][1]),
                          "+f"(acc[ma][na][2]), "+f"(acc[ma][na][3])
                        : "r"(af[ma][0]), "r"(af[ma][1]), "r"(af[ma][2]), "r"(af[ma][3]),
                          "r"(bf[na][0]), "r"(bf[na][1]));
        }
        buf ^= 1;
    }

    const int tm = lane >> 2;
    const int tn = (lane & 3) * 2;
    #pragma unroll
    for (int ma = 0; ma < 4; ma++) {
        #pragma unroll
        for (int na = 0; na < 4; na++) {
            int m = m0 + wr*64 + ma*16 + tm;
            int n = n0 + wc*32 + na*8 + tn;
            float b0 = bias ? bias[n] : 0.f;
            float b1 = bias ? bias[n + 1] : 0.f;
            float v00 = acc[ma][na][0] + b0, v01 = acc[ma][na][1] + b1;
            float v10 = acc[ma][na][2] + b0, v11 = acc[ma][na][3] + b1;
            if (relu) {
                v00 = fmaxf(v00, 0.f); v01 = fmaxf(v01, 0.f);
                v10 = fmaxf(v10, 0.f); v11 = fmaxf(v11, 0.f);
            }
            if (m < M)
                *reinterpret_cast<float2*>(&C[(size_t)m*N + n]) = make_float2(v00, v01);
            if (m + 8 < M)
                *reinterpret_cast<float2*>(&C[(size_t)(m+8)*N + n]) = make_float2(v10, v11);
        }
    }
}

// ---------------------------------------------------------------------------
// c3b HMMA GEMM with fused neighbor-max epilogue
// ---------------------------------------------------------------------------
__global__ void __launch_bounds__(256, 2)
c3b_mma_fused_kernel(const __nv_bfloat16* __restrict__ Acat,
                     const __nv_bfloat16* __restrict__ Bcat,
                     const float* __restrict__ bias,
                     float* __restrict__ xcat)
{
    const int KTOT = 768;
    __shared__ __nv_bfloat16 sA[2][128][40];
    __shared__ __nv_bfloat16 sB[2][128][40];

    const int tid  = threadIdx.x;
    const int wid  = tid >> 5;
    const int lane = tid & 31;
    const int m0 = blockIdx.x * 128;
    const int n0 = blockIdx.y * 128;
    const int wr = wid >> 2;
    const int wc = wid & 3;

    float acc[4][4][4];
    #pragma unroll
    for (int a = 0; a < 4; a++)
        #pragma unroll
        for (int b = 0; b < 4; b++)
            #pragma unroll
            for (int c = 0; c < 4; c++) acc[a][b][c] = 0.f;

    auto load_tile = [&](int buf, int k0) {
        #pragma unroll
        for (int t2 = 0; t2 < 2; t2++) {
            int c   = tid + t2 * 256;
            int row = c >> 2;
            int k8  = (c & 3) * 8;
            cp_async16(&sA[buf][row][k8], Acat + (size_t)(m0 + row)*KTOT + k0 + k8);
            cp_async16(&sB[buf][row][k8], Bcat + (size_t)(n0 + row)*KTOT + k0 + k8);
        }
    };

    load_tile(0, 0);
    cp_commit();
    int buf = 0;
    for (int k0 = 0; k0 < KTOT; k0 += 32) {
        cp_wait0();
        __syncthreads();
        if (k0 + 32 < KTOT) { load_tile(buf ^ 1, k0 + 32); cp_commit(); }

        #pragma unroll
        for (int ks = 0; ks < 2; ks++) {
            const int kb = ks * 16;
            uint32_t af[4][4], bf[4][2];
            #pragma unroll
            for (int ma = 0; ma < 4; ma++) {
                int m = wr*64 + ma*16 + (lane & 15);
                int k = kb + ((lane >> 4) << 3);
                uint32_t addr = (uint32_t)__cvta_generic_to_shared(&sA[buf][m][k]);
                asm volatile("ldmatrix.sync.aligned.m8n8.x4.shared.b16 {%0,%1,%2,%3}, [%4];"
                    : "=r"(af[ma][0]), "=r"(af[ma][1]), "=r"(af[ma][2]), "=r"(af[ma][3])
                    : "r"(addr));
            }
            #pragma unroll
            for (int na = 0; na < 4; na++) {
                int n = wc*32 + na*8 + (lane & 7);
                int k = kb + (lane & 8);
                uint32_t addr = (uint32_t)__cvta_generic_to_shared(&sB[buf][n][k]);
                asm volatile("ldmatrix.sync.aligned.m8n8.x2.shared.b16 {%0,%1}, [%2];"
                    : "=r"(bf[na][0]), "=r"(bf[na][1])
                    : "r"(addr));
            }
            #pragma unroll
            for (int ma = 0; ma < 4; ma++)
                #pragma unroll
                for (int na = 0; na < 4; na++)
                    asm volatile(
                        "mma.sync.aligned.m16n8k16.row.col.f32.bf16.bf16.f32 "
                        "{%0,%1,%2,%3}, {%4,%5,%6,%7}, {%8,%9}, {%0,%1,%2,%3};"
                        : "+f"(acc[ma][na][0]), "+f"(acc[ma][na][1]),
                          "+f"(acc[ma][na][2]), "+f"(acc[ma][na][3])
                        : "r"(af[ma][0]), "r"(af[ma][1]), "r"(af[ma][2]), "r"(af[ma][3]),
                          "r"(bf[na][0]), "r"(bf[na][1]));
        }
        buf ^= 1;
    }

    const int tn2 = (lane & 3) * 2;
    #pragma unroll
    for (int ma = 0; ma < 4; ma++) {
        #pragma unroll
        for (int na = 0; na < 4; na++) {
            float r0 = acc[ma][na][0], r1 = acc[ma][na][1];
            float r2 = acc[ma][na][2], r3 = acc[ma][na][3];
            #pragma unroll
            for (int off = 4; off < 32; off <<= 1) {
                r0 = fmaxf(r0, __shfl_xor_sync(0xFFFFFFFFu, r0, off));
                r1 = fmaxf(r1, __shfl_xor_sync(0xFFFFFFFFu, r1, off));
                r2 = fmaxf(r2, __shfl_xor_sync(0xFFFFFFFFu, r2, off));
                r3 = fmaxf(r3, __shfl_xor_sync(0xFFFFFFFFu, r3, off));
            }
            if (lane < 4) {
                int base = m0 + wr*64 + ma*16;
                int p0 = base >> 3;
                int n  = n0 + wc*32 + na*8 + tn2;
                float b0 = bias[n], b1 = bias[n + 1];
                float* dst0 = &xcat[(size_t)p0*672 + 160 + n];
                float* dst1 = &xcat[(size_t)(p0+1)*672 + 160 + n];
                dst0[0] = r0 + b0; dst0[1] = r1 + b1;
                dst1[0] = r2 + b0; dst1[1] = r3 + b1;
            }
        }
    }
}

// ---------------------------------------------------------------------------
// Fused global max pool + hg matvec
// ---------------------------------------------------------------------------
__global__ void gpool_hg_kernel(const float* __restrict__ sf,
                                const float* __restrict__ w,
                                const float* __restrict__ b1,
                                float* __restrict__ hg)
{
    __shared__ float red[1024];
    __shared__ float sg[128];
    int b = blockIdx.x;
    int c = threadIdx.x & 127;
    int slice = threadIdx.x >> 7;
    float v = -FLT_MAX;
    for (int n = slice; n < NPTS; n += 8)
        v = fmaxf(v, sf[(((size_t)b*NPTS) + n)*128 + c]);
    red[threadIdx.x] = v;
    __syncthreads();
    if (threadIdx.x < 512) red[threadIdx.x] = fmaxf(red[threadIdx.x], red[threadIdx.x+512]);
    __syncthreads();
    if (threadIdx.x < 256) red[threadIdx.x] = fmaxf(red[threadIdx.x], red[threadIdx.x+256]);
    __syncthreads();
    if (threadIdx.x < 128) sg[threadIdx.x] = fmaxf(red[threadIdx.x], red[threadIdx.x+128]);
    __syncthreads();
    if (threadIdx.x < 128) {
        float acc = b1[c];
        for (int k = 0; k < 128; k++)
            acc = fmaf(sg[k], w[k*128 + c], acc);
        hg[b*128 + c] = acc;
    }
}

// ---------------------------------------------------------------------------
// Pair kernel: 128x128 tiles, 256 threads, 8x8 micro, c in 4 chunks of 32
// ---------------------------------------------------------------------------
__global__ void __launch_bounds__(256)
pair_kernel(const float* __restrict__ hh, const float* __restrict__ hgv,
            const float* __restrict__ w2, const float* __restrict__ b2p,
            float* __restrict__ out)
{
    const int b  = blockIdx.z;
    const int i0 = blockIdx.y * 128;
    const int j0 = blockIdx.x * 128;
    if (j0 + 127 <= i0) return;

    __shared__ float shi[128][33];
    __shared__ float shj[128][33];
    __shared__ float sw2[128];
    __shared__ float shg[128];

    const int tid = threadIdx.x;
    const int ti = tid >> 4;
    const int tj = tid & 15;

    if (tid < 128) { sw2[tid] = w2[tid]; shg[tid] = hgv[b*128 + tid]; }

    float acc[8][8];
    #pragma unroll
    for (int q = 0; q < 8; q++)
        #pragma unroll
        for (int s = 0; s < 8; s++) acc[q][s] = 0.f;

    for (int c0 = 0; c0 < 128; c0 += 32) {
        __syncthreads();
        #pragma unroll
        for (int it = 0; it < 16; it++) {
            int idx = tid + it * 256;
            int r = idx >> 5, c = idx & 31;
            int gi = i0 + r, gj = j0 + r;
            shi[r][c] = (gi < NPTS) ? hh[(((size_t)b*NPTS) + gi)*256 + c0 + c] : 0.f;
            shj[r][c] = (gj < NPTS) ? hh[(((size_t)b*NPTS) + gj)*256 + 128 + c0 + c] : 0.f;
        }
        __syncthreads();
        #pragma unroll 4
        for (int c = 0; c < 32; c++) {
            float w = sw2[c0 + c];
            float hgc = shg[c0 + c];
            float ri[8], rj[8];
            #pragma unroll
            for (int q = 0; q < 8; q++) ri[q] = shi[ti*8 + q][c] + hgc;
            #pragma unroll
            for (int s = 0; s < 8; s++) rj[s] = shj[tj + 16*s][c];
            #pragma unroll
            for (int q = 0; q < 8; q++)
                #pragma unroll
                for (int s = 0; s < 8; s++)
                    acc[q][s] = fmaf(fmaxf(ri[q] + rj[s], 0.f), w, acc[q][s]);
        }
    }

    const float bb = b2p[0];
    #pragma unroll
    for (int q = 0; q < 8; q++) {
        int i = i0 + ti*8 + q;
        if (i >= NPTS) continue;
        #pragma unroll
        for (int s = 0; s < 8; s++) {
            int j = j0 + tj + 16*s;
            if (j < NPTS && i < j) {
                float lg = acc[q][s] + bb;
                int p = i*NPTS - (i*(i+1))/2 + (j - i - 1);
                out[(size_t)b*NPAIR + p] = 1.f / (1.f + expf(-lg));
                out[(size_t)BATCH*NPAIR + (size_t)b*NPAIR + p] = lg;
            }
        }
    }
}

// ---------------------------------------------------------------------------
// Launch helpers
// ---------------------------------------------------------------------------
static inline void run_sgemm64(const float* A, const float* W, const float* bias,
                               float* C, int M, int N, int K, int relu)
{
    dim3 grid((N + 63)/64, (M + 63)/64);
    sgemm64_kernel<<<grid, 256>>>(A, W, bias, C, M, N, K, relu);
}
static inline void run_sgemm64_dual(const float* A, const float* Wa, const float* Wb,
                                    const float* bias, float* C, int M, int Nw, int K)
{
    dim3 grid((2*Nw)/64, (M + 63)/64);
    sgemm64_dual_kernel<<<grid, 256>>>(A, Wa, Wb, bias, C, M, Nw, K);
}
template<int C>
static inline void run_knn(const float* x, float* d2, int* knn)
{
    dim3 dgrid((NPTS + 63)/64, (NPTS + 63)/64, BATCH);
    dist_kernel<C><<<dgrid, 256>>>(x, d2);
    dim3 tgrid(NPTS, BATCH);
    topk_kernel<<<tgrid, 128>>>(d2, knn);
}

extern "C" void kernel_launch(void* const* d_in, const int* in_sizes, int n_in,
                              void* d_out, int out_size)
{
    const float* pos   = (const float*)d_in[0];
    const float* c1_w1 = (const float*)d_in[1];
    const float* c1_b1 = (const float*)d_in[2];
    const float* c1_w2 = (const float*)d_in[3];
    const float* c1_b2 = (const float*)d_in[4];
    const float* c2_w1 = (const float*)d_in[5];
    const float* c2_b1 = (const float*)d_in[6];
    const float* c2_w2 = (const float*)d_in[7];
    const float* c2_b2 = (const float*)d_in[8];
    const float* c3_w1 = (const float*)d_in[9];
    const float* c3_b1 = (const float*)d_in[10];
    const float* c3_w2 = (const float*)d_in[11];
    const float* c3_b2 = (const float*)d_in[12];
    const float* sm_w1 = (const float*)d_in[13];
    const float* sm_b1 = (const float*)d_in[14];
    const float* sm_w2 = (const float*)d_in[15];
    const float* sm_b2 = (const float*)d_in[16];
    const float* ec_w1 = (const float*)d_in[17];
    const float* ec_b1 = (const float*)d_in[18];
    const float* ec_w2 = (const float*)d_in[19];
    const float* ec_b2 = (const float*)d_in[20];

    float* out = (float*)d_out;

    int*   knn;  cudaGetSymbolAddress((void**)&knn,  g_knn);
    float* d2;   cudaGetSymbolAddress((void**)&d2,   g_d2);
    float* Ab;   cudaGetSymbolAddress((void**)&Ab,   g_A);
    float* H;    cudaGetSymbolAddress((void**)&H,    g_H);
    float* T;    cudaGetSymbolAddress((void**)&T,    g_T);
    float* x1;   cudaGetSymbolAddress((void**)&x1,   g_x1);
    float* x2;   cudaGetSymbolAddress((void**)&x2,   g_x2);
    float* xcat; cudaGetSymbolAddress((void**)&xcat, g_xcat);
    float* sf;   cudaGetSymbolAddress((void**)&sf,   g_sf);
    float* hg;   cudaGetSymbolAddress((void**)&hg,   g_hg);
    __nv_bfloat16 *Acat, *Wcat, *Wcat2;
    cudaGetSymbolAddress((void**)&Acat,  g_Acat);
    cudaGetSymbolAddress((void**)&Wcat,  g_Wcat);
    cudaGetSymbolAddress((void**)&Wcat2, g_Wcat2);

    const int ROWS = BATCH*NPTS*KNN;   // 16000
    const int PTS  = BATCH*NPTS;       // 2000

    // ======== weight prep (independent of data path — issued first) ========
    split_w3_kernel<<<dim3(512/32, 256/32), 256>>>(c3_w2, Wcat);
    split_w3_g<<<dim3(256/32, 672/32), 256>>>(sm_w1, Wcat2, 672, 256);

    // ======== EdgeConv 1 (fully fused): pos -> x1 (32) ========
    run_knn<3>(pos, d2, knn);
    ec1_fused_kernel<<<250, 256>>>(pos, knn, c1_w1, c1_b1, c1_w2, c1_b2, x1, xcat);

    // ======== EdgeConv 2: x1 (32) -> x2 (128) ========
    run_knn<32>(x1, d2, knn);
    run_sgemm64_dual(x1, c2_w1, c2_w1 + 32*64, nullptr, Ab, PTS, 64, 32);
    edge_combine_kernel<<<(ROWS*16 + 255)/256, 256>>>(Ab, Ab + 64, 32, knn, c2_b1, H, 16);
    {
        dim3 grid(1, 125);
        c2b_fused_kernel<<<grid, 256>>>(H, c2_w2, c2_b2, x2, xcat);
    }

    // ======== EdgeConv 3: x2 (128) -> x3 (512) ========
    run_knn<128>(x2, d2, knn);
    run_sgemm64_dual(x2, c3_w1, c3_w1 + 128*256, nullptr, T, PTS, 256, 128);
    edge_combine_split_kernel<<<(ROWS*64 + 255)/256, 256>>>(T, T + 256, 128, knn, c3_b1, Acat);
    c3b_mma_fused_kernel<<<dim3(125, 4), 256>>>(Acat, Wcat, c3_b2, xcat);

    // ======== shared MLP: sm1 on HMMA (K'=2016), sm2 fp32 ========
    split_a3_g<<<(PTS*672 + 255)/256, 256>>>(xcat, Acat, PTS*672, 672);
    {
        dim3 grid((PTS + 127)/128, 256/128);
        mma_g_kernel<<<grid, 256>>>(Acat, Wcat2, sm_b1, H, PTS, 256, 2016, 1);
    }
    run_sgemm64(H, sm_w2, sm_b2, sf, PTS, 128, 256, 0);

    // ======== global pool + hg (fused) + hh dual-GEMM ========
    gpool_hg_kernel<<<BATCH, 1024>>>(sf, ec_w1 + 256*128, ec_b1, hg);
    run_sgemm64_dual(sf, ec_w1, ec_w1 + 128*128, nullptr, Ab, PTS, 128, 128);

    // ======== all-pairs classifier ========
    {
        dim3 grid((NPTS + 127)/128, (NPTS + 127)/128, BATCH);
        pair_kernel<<<grid, 256>>>(Ab, hg, ec_w2, ec_b2, out);
    }
}

// round 15
// speedup vs baseline: 1.5123x; 1.5123x over previous
#include <cuda_runtime.h>
#include <cuda_bf16.h>
#include <math.h>
#include <float.h>
#include <stdint.h>

#define BATCH 2
#define NPTS  1000
#define KNN   8
#define NPAIR ((NPTS*(NPTS-1))/2)   // 499500

// ---------------------------------------------------------------------------
// Static scratch
// ---------------------------------------------------------------------------
__device__ int   g_knn [BATCH*NPTS*KNN];
__device__ float g_d2  [BATCH*NPTS*NPTS];      // 8 MB distance matrix
__device__ float g_A   [BATCH*NPTS*256];       // c2a AB / hh [2000][256]
__device__ float g_H   [BATCH*NPTS*KNN*256];   // stage-2 edge hidden / sm hidden
__device__ float g_T   [BATCH*NPTS*512];       // c3a AB [2000][512]
__device__ float g_x1  [BATCH*NPTS*32];
__device__ float g_x2  [BATCH*NPTS*128];
__device__ float g_xcat[BATCH*NPTS*672];
__device__ float g_sf  [BATCH*NPTS*128];
__device__ float g_hg  [BATCH*128];
// bf16 split-concat buffers for the HMMA c3b GEMM (K' = 3*256 = 768)
__device__ __nv_bfloat16 g_Acat[16000*768];
__device__ __nv_bfloat16 g_Wcat[512*768];

// ---------------------------------------------------------------------------
// cp.async helpers
// ---------------------------------------------------------------------------
__device__ __forceinline__ void cp_async16(void* smem_ptr, const void* gmem_ptr) {
    unsigned dst = (unsigned)__cvta_generic_to_shared(smem_ptr);
    asm volatile("cp.async.cg.shared.global [%0], [%1], 16;\n" :: "r"(dst), "l"(gmem_ptr));
}
__device__ __forceinline__ void cp_commit() { asm volatile("cp.async.commit_group;\n" ::: "memory"); }
__device__ __forceinline__ void cp_wait0()  { asm volatile("cp.async.wait_group 0;\n" ::: "memory"); }

// ---------------------------------------------------------------------------
// Pairwise distance with inline row-norms (64x64, 4x4 micro — R11-proven)
// ---------------------------------------------------------------------------
template<int C>
__global__ void __launch_bounds__(256)
dist_kernel(const float* __restrict__ x, float* __restrict__ d2)
{
    const int b  = blockIdx.z;
    const int n0 = blockIdx.y * 64;
    const int m0 = blockIdx.x * 64;
    const float* xb = x + (size_t)b * NPTS * C;

    __shared__ float As[32][68];
    __shared__ float Bs[32][68];

    const int tid = threadIdx.x;
    const int ti = tid >> 4;
    const int tj = tid & 15;

    float acc[4][4];
    float sqa[4], sqbv[4];
    #pragma unroll
    for (int i = 0; i < 4; i++) { sqa[i] = 0.f; sqbv[i] = 0.f; }
    #pragma unroll
    for (int i = 0; i < 4; i++)
        #pragma unroll
        for (int j = 0; j < 4; j++) acc[i][j] = 0.f;

    for (int k0 = 0; k0 < C; k0 += 32) {
        #pragma unroll
        for (int v = tid; v < 512; v += 256) {
            int r  = v >> 3;
            int cq = (v & 7) * 4;
            {
                int row = n0 + r;
                float4 a4 = make_float4(0.f, 0.f, 0.f, 0.f);
                if (row < NPTS) {
                    if ((C & 31) == 0) {
                        a4 = *reinterpret_cast<const float4*>(&xb[(size_t)row*C + k0 + cq]);
                    } else {
                        float tmp[4];
                        #pragma unroll
                        for (int t2 = 0; t2 < 4; t2++) {
                            int k = k0 + cq + t2;
                            tmp[t2] = (k < C) ? xb[(size_t)row*C + k] : 0.f;
                        }
                        a4 = make_float4(tmp[0], tmp[1], tmp[2], tmp[3]);
                    }
                }
                As[cq+0][r] = a4.x; As[cq+1][r] = a4.y;
                As[cq+2][r] = a4.z; As[cq+3][r] = a4.w;
            }
            {
                int row = m0 + r;
                float4 b4 = make_float4(0.f, 0.f, 0.f, 0.f);
                if (row < NPTS) {
                    if ((C & 31) == 0) {
                        b4 = *reinterpret_cast<const float4*>(&xb[(size_t)row*C + k0 + cq]);
                    } else {
                        float tmp[4];
                        #pragma unroll
                        for (int t2 = 0; t2 < 4; t2++) {
                            int k = k0 + cq + t2;
                            tmp[t2] = (k < C) ? xb[(size_t)row*C + k] : 0.f;
                        }
                        b4 = make_float4(tmp[0], tmp[1], tmp[2], tmp[3]);
                    }
                }
                Bs[cq+0][r] = b4.x; Bs[cq+1][r] = b4.y;
                Bs[cq+2][r] = b4.z; Bs[cq+3][r] = b4.w;
            }
        }
        __syncthreads();
        #pragma unroll
        for (int kk = 0; kk < 32; kk++) {
            float ra[4], rb[4];
            *reinterpret_cast<float4*>(ra) = *reinterpret_cast<const float4*>(&As[kk][ti*4]);
            *reinterpret_cast<float4*>(rb) = *reinterpret_cast<const float4*>(&Bs[kk][tj*4]);
            #pragma unroll
            for (int i = 0; i < 4; i++) sqa[i]  = fmaf(ra[i], ra[i], sqa[i]);
            #pragma unroll
            for (int j = 0; j < 4; j++) sqbv[j] = fmaf(rb[j], rb[j], sqbv[j]);
            #pragma unroll
            for (int i = 0; i < 4; i++)
                #pragma unroll
                for (int j = 0; j < 4; j++)
                    acc[i][j] = fmaf(ra[i], rb[j], acc[i][j]);
        }
        __syncthreads();
    }

    const int ni = n0 + ti*4;
    const int mj = m0 + tj*4;
    #pragma unroll
    for (int i = 0; i < 4; i++) {
        if (ni+i >= NPTS) continue;
        #pragma unroll
        for (int j = 0; j < 4; j++) {
            if (mj+j >= NPTS) continue;
            d2[((size_t)b*NPTS + ni+i)*NPTS + mj+j] = sqa[i] + sqbv[j] - 2.f*acc[i][j];
        }
    }
}

// ---------------------------------------------------------------------------
// Top-8 per row, warp-per-row EXTRACTION (zero dynamic indexing).
// Lane holds 32 statically-indexed register values + extracted-bit mask.
// 8 rounds of (masked static min-scan -> shfl argmin with (d,idx) tie-break).
// Strict total order => identical result to the reference stable top-8.
// ---------------------------------------------------------------------------
__global__ void __launch_bounds__(256)
topk_extract_kernel(const float* __restrict__ d2, int* __restrict__ knn)
{
    const int warp = threadIdx.x >> 5;
    const int lane = threadIdx.x & 31;
    const int rid  = blockIdx.x * 8 + warp;   // 0..1999
    if (rid >= BATCH*NPTS) return;
    const float* row = d2 + (size_t)rid * NPTS;

    float vals[32];
    #pragma unroll
    for (int e = 0; e < 32; e++) {
        int m = e * 32 + lane;
        vals[e] = (m < NPTS) ? row[m] : FLT_MAX;
    }

    unsigned mask = 0;
    #pragma unroll
    for (int k = 0; k < 8; k++) {
        float bm = FLT_MAX;
        int   bi = 0x7FFFFFFF;
        int   be = -1;
        #pragma unroll
        for (int e = 0; e < 32; e++) {
            int m = e * 32 + lane;
            bool live = !((mask >> e) & 1u);
            bool better = live && (vals[e] < bm || (vals[e] == bm && m < bi));
            if (better) { bm = vals[e]; bi = m; be = e; }
        }
        float wm = bm;
        int   wi = bi;
        #pragma unroll
        for (int off = 16; off >= 1; off >>= 1) {
            float om = __shfl_xor_sync(0xFFFFFFFFu, wm, off);
            int   oi = __shfl_xor_sync(0xFFFFFFFFu, wi, off);
            if (om < wm || (om == wm && oi < wi)) { wm = om; wi = oi; }
        }
        if (wi == bi && be >= 0) mask |= 1u << be;   // unique owner (global idx unique)
        if (lane == 0) knn[(size_t)rid*8 + k] = wi;
    }
}

// ---------------------------------------------------------------------------
// Fully fused EdgeConv1 (one warp per point) — R13 version
// ---------------------------------------------------------------------------
__global__ void __launch_bounds__(256)
ec1_fused_kernel(const float* __restrict__ pos, const int* __restrict__ knn,
                 const float* __restrict__ W1, const float* __restrict__ b1,
                 const float* __restrict__ W2, const float* __restrict__ b2,
                 float* __restrict__ x1, float* __restrict__ xcat)
{
    __shared__ float sW1[96], sb1[16], sW2[512], sb2[32];
    const int tid = threadIdx.x;
    if (tid < 96) sW1[tid] = W1[tid];
    if (tid < 16) sb1[tid] = b1[tid];
    if (tid < 32) sb2[tid] = b2[tid];
    for (int t = tid; t < 512; t += 256) sW2[t] = W2[t];
    __syncthreads();

    const int warp = tid >> 5, lane = tid & 31;
    const int p = blockIdx.x * 8 + warp;
    if (p >= BATCH*NPTS) return;
    const int b = p / NPTS;

    const float* xi = pos + (size_t)p*3;
    const float xi0 = xi[0], xi1 = xi[1], xi2 = xi[2];

    float best = -FLT_MAX;
    #pragma unroll
    for (int e = 0; e < 8; e++) {
        int j = knn[p*8 + e];
        const float* xj = pos + ((size_t)b*NPTS + j)*3;
        float d0 = xj[0]-xi0, d1 = xj[1]-xi1, d2v = xj[2]-xi2;
        float macc = 0.f;
        #pragma unroll
        for (int k = 0; k < 16; k++) {
            float h = sb1[k];
            h = fmaf(xi0, sW1[0*16+k], h);
            h = fmaf(d0,  sW1[3*16+k], h);
            h = fmaf(xi1, sW1[1*16+k], h);
            h = fmaf(d1,  sW1[4*16+k], h);
            h = fmaf(xi2, sW1[2*16+k], h);
            h = fmaf(d2v, sW1[5*16+k], h);
            h = fmaxf(h, 0.f);
            macc = fmaf(h, sW2[k*32 + lane], macc);
        }
        best = fmaxf(best, macc + sb2[lane]);
    }
    x1[(size_t)p*32 + lane] = best;
    xcat[(size_t)p*672 + lane] = best;
}

// ---------------------------------------------------------------------------
// SGEMM64 with register-prefetch pipeline (row-major A). K%16==0, N%64==0.
// ---------------------------------------------------------------------------
__global__ void __launch_bounds__(256)
sgemm64_kernel(const float* __restrict__ A, const float* __restrict__ W,
               const float* __restrict__ bias, float* __restrict__ C,
               int M, int N, int K, int relu)
{
    __shared__ float As[16][64];
    __shared__ float Bs[16][64];

    const int tid = threadIdx.x;
    const int tx = tid & 15;
    const int ty = tid >> 4;
    const int row0 = blockIdx.y * 64;
    const int col0 = blockIdx.x * 64;

    const int lm  = tid >> 2;
    const int lkq = (tid & 3) * 4;
    const int lkk = tid >> 4;
    const int ln4 = (tid & 15) * 4;

    float acc[4][4];
    #pragma unroll
    for (int i = 0; i < 4; i++)
        #pragma unroll
        for (int j = 0; j < 4; j++) acc[i][j] = 0.f;

    auto loadA = [&](int k0) -> float4 {
        int gm = min(row0 + lm, M - 1);
        return *reinterpret_cast<const float4*>(&A[(size_t)gm * K + k0 + lkq]);
    };
    auto loadB = [&](int k0) -> float4 {
        return *reinterpret_cast<const float4*>(&W[(size_t)(k0 + lkk) * N + col0 + ln4]);
    };

    float4 ra4 = loadA(0);
    float4 rb4 = loadB(0);

    for (int k0 = 0; k0 < K; k0 += 16) {
        As[lkq+0][lm] = ra4.x; As[lkq+1][lm] = ra4.y;
        As[lkq+2][lm] = ra4.z; As[lkq+3][lm] = ra4.w;
        *reinterpret_cast<float4*>(&Bs[lkk][ln4]) = rb4;
        __syncthreads();
        if (k0 + 16 < K) { ra4 = loadA(k0 + 16); rb4 = loadB(k0 + 16); }
        #pragma unroll
        for (int kk = 0; kk < 16; kk++) {
            float ra[4], rb[4];
            *reinterpret_cast<float4*>(ra) = *reinterpret_cast<const float4*>(&As[kk][ty*4]);
            *reinterpret_cast<float4*>(rb) = *reinterpret_cast<const float4*>(&Bs[kk][tx*4]);
            #pragma unroll
            for (int i = 0; i < 4; i++)
                #pragma unroll
                for (int j = 0; j < 4; j++)
                    acc[i][j] = fmaf(ra[i], rb[j], acc[i][j]);
        }
        __syncthreads();
    }
    #pragma unroll
    for (int i = 0; i < 4; i++) {
        int gm = row0 + ty*4 + i;
        if (gm >= M) continue;
        #pragma unroll
        for (int j = 0; j < 4; j++) {
            int gn = col0 + tx*4 + j;
            float v = acc[i][j];
            if (bias) v += bias[gn];
            if (relu) v = fmaxf(v, 0.f);
            C[(size_t)gm * N + gn] = v;
        }
    }
}

// ---------------------------------------------------------------------------
// Dual-weight SGEMM64 with register-prefetch pipeline (c2a / c3a / hh)
// ---------------------------------------------------------------------------
__global__ void __launch_bounds__(256)
sgemm64_dual_kernel(const float* __restrict__ A,
                    const float* __restrict__ Wa, const float* __restrict__ Wb,
                    const float* __restrict__ bias,
                    float* __restrict__ C,
                    int M, int Nw, int K)
{
    __shared__ float As[16][64];
    __shared__ float Bs[16][64];

    const int tid = threadIdx.x;
    const int tx = tid & 15;
    const int ty = tid >> 4;
    const int row0 = blockIdx.y * 64;
    const int col0 = blockIdx.x * 64;
    const int Ntot = 2 * Nw;
    const float* W = (col0 < Nw) ? Wa : Wb;
    const int colw0 = (col0 < Nw) ? col0 : col0 - Nw;

    const int lm  = tid >> 2;
    const int lkq = (tid & 3) * 4;
    const int lkk = tid >> 4;
    const int ln4 = (tid & 15) * 4;

    float acc[4][4];
    #pragma unroll
    for (int i = 0; i < 4; i++)
        #pragma unroll
        for (int j = 0; j < 4; j++) acc[i][j] = 0.f;

    auto loadA = [&](int k0) -> float4 {
        int gm = min(row0 + lm, M - 1);
        return *reinterpret_cast<const float4*>(&A[(size_t)gm * K + k0 + lkq]);
    };
    auto loadB = [&](int k0) -> float4 {
        return *reinterpret_cast<const float4*>(&W[(size_t)(k0 + lkk) * Nw + colw0 + ln4]);
    };

    float4 ra4 = loadA(0);
    float4 rb4 = loadB(0);

    for (int k0 = 0; k0 < K; k0 += 16) {
        As[lkq+0][lm] = ra4.x; As[lkq+1][lm] = ra4.y;
        As[lkq+2][lm] = ra4.z; As[lkq+3][lm] = ra4.w;
        *reinterpret_cast<float4*>(&Bs[lkk][ln4]) = rb4;
        __syncthreads();
        if (k0 + 16 < K) { ra4 = loadA(k0 + 16); rb4 = loadB(k0 + 16); }
        #pragma unroll
        for (int kk = 0; kk < 16; kk++) {
            float ra[4], rb[4];
            *reinterpret_cast<float4*>(ra) = *reinterpret_cast<const float4*>(&As[kk][ty*4]);
            *reinterpret_cast<float4*>(rb) = *reinterpret_cast<const float4*>(&Bs[kk][tx*4]);
            #pragma unroll
            for (int i = 0; i < 4; i++)
                #pragma unroll
                for (int j = 0; j < 4; j++)
                    acc[i][j] = fmaf(ra[i], rb[j], acc[i][j]);
        }
        __syncthreads();
    }
    #pragma unroll
    for (int i = 0; i < 4; i++) {
        int gm = row0 + ty*4 + i;
        if (gm >= M) continue;
        #pragma unroll
        for (int j = 0; j < 4; j++) {
            int gn = col0 + tx*4 + j;
            float v = acc[i][j];
            if (bias) v += bias[gn];
            C[(size_t)gm * Ntot + gn] = v;
        }
    }
}

// ---------------------------------------------------------------------------
// c2b SGEMM128 with fused neighbor-max epilogue (M=16000, N=128, K=64)
// ---------------------------------------------------------------------------
__global__ void __launch_bounds__(256, 2)
c2b_fused_kernel(const float* __restrict__ A, const float* __restrict__ W,
                 const float* __restrict__ bias,
                 float* __restrict__ x2, float* __restrict__ xcat)
{
    const int BK = 16, N = 128, K = 64;
    __shared__ float As[BK][128];
    __shared__ float Bs[BK][128];

    const int tid = threadIdx.x;
    const int tx = tid & 15;
    const int ty = tid >> 4;
    const int row0 = blockIdx.y * 128;

    float acc[8][8];
    #pragma unroll
    for (int i = 0; i < 8; i++)
        #pragma unroll
        for (int j = 0; j < 8; j++) acc[i][j] = 0.f;

    for (int k0 = 0; k0 < K; k0 += BK) {
        #pragma unroll
        for (int t = 0; t < 2; t++) {
            int v  = tid + t * 256;
            int m  = v >> 2;
            int kq = (v & 3) * 4;
            float4 a4 = *reinterpret_cast<const float4*>(&A[(size_t)(row0 + m) * K + k0 + kq]);
            As[kq+0][m] = a4.x; As[kq+1][m] = a4.y;
            As[kq+2][m] = a4.z; As[kq+3][m] = a4.w;
        }
        #pragma unroll
        for (int t = 0; t < 2; t++) {
            int v  = tid + t * 256;
            int n4 = (v & 31) * 4;
            int kk = v >> 5;
            float4 b4 = *reinterpret_cast<const float4*>(&W[(size_t)(k0 + kk) * N + n4]);
            *reinterpret_cast<float4*>(&Bs[kk][n4]) = b4;
        }
        __syncthreads();
        #pragma unroll
        for (int kk = 0; kk < BK; kk++) {
            float ra[8], rb[8];
            *reinterpret_cast<float4*>(&ra[0]) = *reinterpret_cast<const float4*>(&As[kk][ty*8]);
            *reinterpret_cast<float4*>(&ra[4]) = *reinterpret_cast<const float4*>(&As[kk][ty*8+4]);
            *reinterpret_cast<float4*>(&rb[0]) = *reinterpret_cast<const float4*>(&Bs[kk][tx*8]);
            *reinterpret_cast<float4*>(&rb[4]) = *reinterpret_cast<const float4*>(&Bs[kk][tx*8+4]);
            #pragma unroll
            for (int i = 0; i < 8; i++)
                #pragma unroll
                for (int j = 0; j < 8; j++)
                    acc[i][j] = fmaf(ra[i], rb[j], acc[i][j]);
        }
        __syncthreads();
    }

    const int p = (row0 + ty*8) >> 3;
    float mx[8];
    #pragma unroll
    for (int j = 0; j < 8; j++) {
        float v = acc[0][j];
        #pragma unroll
        for (int i = 1; i < 8; i++) v = fmaxf(v, acc[i][j]);
        mx[j] = v + bias[tx*8 + j];
    }
    *reinterpret_cast<float4*>(&x2[(size_t)p*128 + tx*8])     = *reinterpret_cast<float4*>(&mx[0]);
    *reinterpret_cast<float4*>(&x2[(size_t)p*128 + tx*8 + 4]) = *reinterpret_cast<float4*>(&mx[4]);
    *reinterpret_cast<float4*>(&xcat[(size_t)p*672 + 32 + tx*8])     = *reinterpret_cast<float4*>(&mx[0]);
    *reinterpret_cast<float4*>(&xcat[(size_t)p*672 + 32 + tx*8 + 4]) = *reinterpret_cast<float4*>(&mx[4]);
}

// ---------------------------------------------------------------------------
// Stage-2 edge combine (fp32 H output)
// ---------------------------------------------------------------------------
__global__ void edge_combine_kernel(const float* __restrict__ A,
                                    const float* __restrict__ Bv,
                                    int lda4,
                                    const int* __restrict__ knn,
                                    const float* __restrict__ b1,
                                    float* __restrict__ H, int Nh4)
{
    int t = blockIdx.x * blockDim.x + threadIdx.x;
    int all = BATCH*NPTS*KNN*Nh4;
    if (t >= all) return;
    int c4 = t % Nh4;
    int e  = t / Nh4;
    int n  = (e / KNN) % NPTS;
    int b  = e / (KNN*NPTS);
    int j  = knn[e];
    size_t pi = (size_t)b*NPTS + n;
    size_t pj = (size_t)b*NPTS + j;
    float4 a  = reinterpret_cast<const float4*>(A)[pi*lda4 + c4];
    float4 bi = reinterpret_cast<const float4*>(Bv)[pi*lda4 + c4];
    float4 bj = reinterpret_cast<const float4*>(Bv)[pj*lda4 + c4];
    float4 bb = reinterpret_cast<const float4*>(b1)[c4];
    float4 h;
    h.x = fmaxf(a.x + bj.x - bi.x + bb.x, 0.f);
    h.y = fmaxf(a.y + bj.y - bi.y + bb.y, 0.f);
    h.z = fmaxf(a.z + bj.z - bi.z + bb.z, 0.f);
    h.w = fmaxf(a.w + bj.w - bi.w + bb.w, 0.f);
    reinterpret_cast<float4*>(H)[(size_t)e*Nh4 + c4] = h;
}

// ---------------------------------------------------------------------------
// Stage-3 edge combine + bf16 split -> Acat[e][768] = [hi|hi|lo]
// ---------------------------------------------------------------------------
__global__ void edge_combine_split_kernel(const float* __restrict__ A,
                                          const float* __restrict__ Bv,
                                          int lda4,
                                          const int* __restrict__ knn,
                                          const float* __restrict__ b1,
                                          __nv_bfloat16* __restrict__ Acat)
{
    int t = blockIdx.x * blockDim.x + threadIdx.x;
    int all = BATCH*NPTS*KNN*64;
    if (t >= all) return;
    int c4 = t & 63;
    int e  = t >> 6;
    int n  = (e / KNN) % NPTS;
    int b  = e / (KNN*NPTS);
    int j  = knn[e];
    size_t pi = (size_t)b*NPTS + n;
    size_t pj = (size_t)b*NPTS + j;
    float4 a  = reinterpret_cast<const float4*>(A)[pi*lda4 + c4];
    float4 bi = reinterpret_cast<const float4*>(Bv)[pi*lda4 + c4];
    float4 bj = reinterpret_cast<const float4*>(Bv)[pj*lda4 + c4];
    float4 bb = reinterpret_cast<const float4*>(b1)[c4];
    float h0 = fmaxf(a.x + bj.x - bi.x + bb.x, 0.f);
    float h1 = fmaxf(a.y + bj.y - bi.y + bb.y, 0.f);
    float h2 = fmaxf(a.z + bj.z - bi.z + bb.z, 0.f);
    float h3 = fmaxf(a.w + bj.w - bi.w + bb.w, 0.f);

    __nv_bfloat16 H0 = __float2bfloat16(h0), H1 = __float2bfloat16(h1);
    __nv_bfloat16 H2 = __float2bfloat16(h2), H3 = __float2bfloat16(h3);
    __nv_bfloat16 L0 = __float2bfloat16(h0 - __bfloat162float(H0));
    __nv_bfloat16 L1 = __float2bfloat16(h1 - __bfloat162float(H1));
    __nv_bfloat16 L2 = __float2bfloat16(h2 - __bfloat162float(H2));
    __nv_bfloat16 L3 = __float2bfloat16(h3 - __bfloat162float(H3));

    size_t base = (size_t)e * 768 + c4*4;
    __nv_bfloat162* p0 = reinterpret_cast<__nv_bfloat162*>(&Acat[base]);
    __nv_bfloat162* p1 = reinterpret_cast<__nv_bfloat162*>(&Acat[base + 256]);
    __nv_bfloat162* p2 = reinterpret_cast<__nv_bfloat162*>(&Acat[base + 512]);
    __nv_bfloat162 hiA; hiA.x = H0; hiA.y = H1;
    __nv_bfloat162 hiB; hiB.x = H2; hiB.y = H3;
    __nv_bfloat162 loA; loA.x = L0; loA.y = L1;
    __nv_bfloat162 loB; loB.x = L2; loB.y = L3;
    p0[0] = hiA; p0[1] = hiB;
    p1[0] = hiA; p1[1] = hiB;
    p2[0] = loA; p2[1] = loB;
}

// ---------------------------------------------------------------------------
// c3b weight split
// ---------------------------------------------------------------------------
__global__ void split_w3_kernel(const float* __restrict__ W,
                                __nv_bfloat16* __restrict__ Bcat)
{
    __shared__ float tile[32][33];
    int n0 = blockIdx.x * 32, k0 = blockIdx.y * 32;
    int tx = threadIdx.x & 31, ty = threadIdx.x >> 5;
    for (int r = ty; r < 32; r += 8) tile[r][tx] = W[(size_t)(k0+r)*512 + n0 + tx];
    __syncthreads();
    for (int r = ty; r < 32; r += 8) {
        float v = tile[tx][r];
        int n = n0 + r, k = k0 + tx;
        __nv_bfloat16 h = __float2bfloat16(v);
        __nv_bfloat16 l = __float2bfloat16(v - __bfloat162float(h));
        size_t base = (size_t)n * 768;
        Bcat[base + k]       = h;
        Bcat[base + 256 + k] = l;
        Bcat[base + 512 + k] = h;
    }
}

// ---------------------------------------------------------------------------
// c3b HMMA GEMM with fused neighbor-max epilogue
// ---------------------------------------------------------------------------
__global__ void __launch_bounds__(256, 2)
c3b_mma_fused_kernel(const __nv_bfloat16* __restrict__ Acat,
                     const __nv_bfloat16* __restrict__ Bcat,
                     const float* __restrict__ bias,
                     float* __restrict__ xcat)
{
    const int KTOT = 768;
    __shared__ __nv_bfloat16 sA[2][128][40];
    __shared__ __nv_bfloat16 sB[2][128][40];

    const int tid  = threadIdx.x;
    const int wid  = tid >> 5;
    const int lane = tid & 31;
    const int m0 = blockIdx.x * 128;
    const int n0 = blockIdx.y * 128;
    const int wr = wid >> 2;
    const int wc = wid & 3;

    float acc[4][4][4];
    #pragma unroll
    for (int a = 0; a < 4; a++)
        #pragma unroll
        for (int b = 0; b < 4; b++)
            #pragma unroll
            for (int c = 0; c < 4; c++) acc[a][b][c] = 0.f;

    auto load_tile = [&](int buf, int k0) {
        #pragma unroll
        for (int t2 = 0; t2 < 2; t2++) {
            int c   = tid + t2 * 256;
            int row = c >> 2;
            int k8  = (c & 3) * 8;
            cp_async16(&sA[buf][row][k8], Acat + (size_t)(m0 + row)*KTOT + k0 + k8);
            cp_async16(&sB[buf][row][k8], Bcat + (size_t)(n0 + row)*KTOT + k0 + k8);
        }
    };

    load_tile(0, 0);
    cp_commit();
    int buf = 0;
    for (int k0 = 0; k0 < KTOT; k0 += 32) {
        cp_wait0();
        __syncthreads();
        if (k0 + 32 < KTOT) { load_tile(buf ^ 1, k0 + 32); cp_commit(); }

        #pragma unroll
        for (int ks = 0; ks < 2; ks++) {
            const int kb = ks * 16;
            uint32_t af[4][4], bf[4][2];
            #pragma unroll
            for (int ma = 0; ma < 4; ma++) {
                int m = wr*64 + ma*16 + (lane & 15);
                int k = kb + ((lane >> 4) << 3);
                uint32_t addr = (uint32_t)__cvta_generic_to_shared(&sA[buf][m][k]);
                asm volatile("ldmatrix.sync.aligned.m8n8.x4.shared.b16 {%0,%1,%2,%3}, [%4];"
                    : "=r"(af[ma][0]), "=r"(af[ma][1]), "=r"(af[ma][2]), "=r"(af[ma][3])
                    : "r"(addr));
            }
            #pragma unroll
            for (int na = 0; na < 4; na++) {
                int n = wc*32 + na*8 + (lane & 7);
                int k = kb + (lane & 8);
                uint32_t addr = (uint32_t)__cvta_generic_to_shared(&sB[buf][n][k]);
                asm volatile("ldmatrix.sync.aligned.m8n8.x2.shared.b16 {%0,%1}, [%2];"
                    : "=r"(bf[na][0]), "=r"(bf[na][1])
                    : "r"(addr));
            }
            #pragma unroll
            for (int ma = 0; ma < 4; ma++)
                #pragma unroll
                for (int na = 0; na < 4; na++)
                    asm volatile(
                        "mma.sync.aligned.m16n8k16.row.col.f32.bf16.bf16.f32 "
                        "{%0,%1,%2,%3}, {%4,%5,%6,%7}, {%8,%9}, {%0,%1,%2,%3};"
                        : "+f"(acc[ma][na][0]), "+f"(acc[ma][na][1]),
                          "+f"(acc[ma][na][2]), "+f"(acc[ma][na][3])
                        : "r"(af[ma][0]), "r"(af[ma][1]), "r"(af[ma][2]), "r"(af[ma][3]),
                          "r"(bf[na][0]), "r"(bf[na][1]));
        }
        buf ^= 1;
    }

    const int tn2 = (lane & 3) * 2;
    #pragma unroll
    for (int ma = 0; ma < 4; ma++) {
        #pragma unroll
        for (int na = 0; na < 4; na++) {
            float r0 = acc[ma][na][0], r1 = acc[ma][na][1];
            float r2 = acc[ma][na][2], r3 = acc[ma][na][3];
            #pragma unroll
            for (int off = 4; off < 32; off <<= 1) {
                r0 = fmaxf(r0, __shfl_xor_sync(0xFFFFFFFFu, r0, off));
                r1 = fmaxf(r1, __shfl_xor_sync(0xFFFFFFFFu, r1, off));
                r2 = fmaxf(r2, __shfl_xor_sync(0xFFFFFFFFu, r2, off));
                r3 = fmaxf(r3, __shfl_xor_sync(0xFFFFFFFFu, r3, off));
            }
            if (lane < 4) {
                int base = m0 + wr*64 + ma*16;
                int p0 = base >> 3;
                int n  = n0 + wc*32 + na*8 + tn2;
                float b0 = bias[n], b1 = bias[n + 1];
                float* dst0 = &xcat[(size_t)p0*672 + 160 + n];
                float* dst1 = &xcat[(size_t)(p0+1)*672 + 160 + n];
                dst0[0] = r0 + b0; dst0[1] = r1 + b1;
                dst1[0] = r2 + b0; dst1[1] = r3 + b1;
            }
        }
    }
}

// ---------------------------------------------------------------------------
// Fused global max pool + hg matvec
// ---------------------------------------------------------------------------
__global__ void gpool_hg_kernel(const float* __restrict__ sf,
                                const float* __restrict__ w,
                                const float* __restrict__ b1,
                                float* __restrict__ hg)
{
    __shared__ float red[1024];
    __shared__ float sg[128];
    int b = blockIdx.x;
    int c = threadIdx.x & 127;
    int slice = threadIdx.x >> 7;
    float v = -FLT_MAX;
    for (int n = slice; n < NPTS; n += 8)
        v = fmaxf(v, sf[(((size_t)b*NPTS) + n)*128 + c]);
    red[threadIdx.x] = v;
    __syncthreads();
    if (threadIdx.x < 512) red[threadIdx.x] = fmaxf(red[threadIdx.x], red[threadIdx.x+512]);
    __syncthreads();
    if (threadIdx.x < 256) red[threadIdx.x] = fmaxf(red[threadIdx.x], red[threadIdx.x+256]);
    __syncthreads();
    if (threadIdx.x < 128) sg[threadIdx.x] = fmaxf(red[threadIdx.x], red[threadIdx.x+128]);
    __syncthreads();
    if (threadIdx.x < 128) {
        float acc = b1[c];
        for (int k = 0; k < 128; k++)
            acc = fmaf(sg[k], w[k*128 + c], acc);
        hg[b*128 + c] = acc;
    }
}

// ---------------------------------------------------------------------------
// Pair kernel: 128x128 tiles, 256 threads, 8x8 micro, c in 4 chunks of 32
// ---------------------------------------------------------------------------
__global__ void __launch_bounds__(256)
pair_kernel(const float* __restrict__ hh, const float* __restrict__ hgv,
            const float* __restrict__ w2, const float* __restrict__ b2p,
            float* __restrict__ out)
{
    const int b  = blockIdx.z;
    const int i0 = blockIdx.y * 128;
    const int j0 = blockIdx.x * 128;
    if (j0 + 127 <= i0) return;

    __shared__ float shi[128][33];
    __shared__ float shj[128][33];
    __shared__ float sw2[128];
    __shared__ float shg[128];

    const int tid = threadIdx.x;
    const int ti = tid >> 4;
    const int tj = tid & 15;

    if (tid < 128) { sw2[tid] = w2[tid]; shg[tid] = hgv[b*128 + tid]; }

    float acc[8][8];
    #pragma unroll
    for (int q = 0; q < 8; q++)
        #pragma unroll
        for (int s = 0; s < 8; s++) acc[q][s] = 0.f;

    for (int c0 = 0; c0 < 128; c0 += 32) {
        __syncthreads();
        #pragma unroll
        for (int it = 0; it < 16; it++) {
            int idx = tid + it * 256;
            int r = idx >> 5, c = idx & 31;
            int gi = i0 + r, gj = j0 + r;
            shi[r][c] = (gi < NPTS) ? hh[(((size_t)b*NPTS) + gi)*256 + c0 + c] : 0.f;
            shj[r][c] = (gj < NPTS) ? hh[(((size_t)b*NPTS) + gj)*256 + 128 + c0 + c] : 0.f;
        }
        __syncthreads();
        #pragma unroll 4
        for (int c = 0; c < 32; c++) {
            float w = sw2[c0 + c];
            float hgc = shg[c0 + c];
            float ri[8], rj[8];
            #pragma unroll
            for (int q = 0; q < 8; q++) ri[q] = shi[ti*8 + q][c] + hgc;
            #pragma unroll
            for (int s = 0; s < 8; s++) rj[s] = shj[tj + 16*s][c];
            #pragma unroll
            for (int q = 0; q < 8; q++)
                #pragma unroll
                for (int s = 0; s < 8; s++)
                    acc[q][s] = fmaf(fmaxf(ri[q] + rj[s], 0.f), w, acc[q][s]);
        }
    }

    const float bb = b2p[0];
    #pragma unroll
    for (int q = 0; q < 8; q++) {
        int i = i0 + ti*8 + q;
        if (i >= NPTS) continue;
        #pragma unroll
        for (int s = 0; s < 8; s++) {
            int j = j0 + tj + 16*s;
            if (j < NPTS && i < j) {
                float lg = acc[q][s] + bb;
                int p = i*NPTS - (i*(i+1))/2 + (j - i - 1);
                out[(size_t)b*NPAIR + p] = 1.f / (1.f + expf(-lg));
                out[(size_t)BATCH*NPAIR + (size_t)b*NPAIR + p] = lg;
            }
        }
    }
}

// ---------------------------------------------------------------------------
// Launch helpers
// ---------------------------------------------------------------------------
static inline void run_sgemm64(const float* A, const float* W, const float* bias,
                               float* C, int M, int N, int K, int relu)
{
    dim3 grid((N + 63)/64, (M + 63)/64);
    sgemm64_kernel<<<grid, 256>>>(A, W, bias, C, M, N, K, relu);
}
static inline void run_sgemm64_dual(const float* A, const float* Wa, const float* Wb,
                                    const float* bias, float* C, int M, int Nw, int K)
{
    dim3 grid((2*Nw)/64, (M + 63)/64);
    sgemm64_dual_kernel<<<grid, 256>>>(A, Wa, Wb, bias, C, M, Nw, K);
}
template<int C>
static inline void run_knn(const float* x, float* d2, int* knn)
{
    dim3 dgrid((NPTS + 63)/64, (NPTS + 63)/64, BATCH);
    dist_kernel<C><<<dgrid, 256>>>(x, d2);
    topk_extract_kernel<<<(BATCH*NPTS + 7)/8, 256>>>(d2, knn);
}

extern "C" void kernel_launch(void* const* d_in, const int* in_sizes, int n_in,
                              void* d_out, int out_size)
{
    const float* pos   = (const float*)d_in[0];
    const float* c1_w1 = (const float*)d_in[1];
    const float* c1_b1 = (const float*)d_in[2];
    const float* c1_w2 = (const float*)d_in[3];
    const float* c1_b2 = (const float*)d_in[4];
    const float* c2_w1 = (const float*)d_in[5];
    const float* c2_b1 = (const float*)d_in[6];
    const float* c2_w2 = (const float*)d_in[7];
    const float* c2_b2 = (const float*)d_in[8];
    const float* c3_w1 = (const float*)d_in[9];
    const float* c3_b1 = (const float*)d_in[10];
    const float* c3_w2 = (const float*)d_in[11];
    const float* c3_b2 = (const float*)d_in[12];
    const float* sm_w1 = (const float*)d_in[13];
    const float* sm_b1 = (const float*)d_in[14];
    const float* sm_w2 = (const float*)d_in[15];
    const float* sm_b2 = (const float*)d_in[16];
    const float* ec_w1 = (const float*)d_in[17];
    const float* ec_b1 = (const float*)d_in[18];
    const float* ec_w2 = (const float*)d_in[19];
    const float* ec_b2 = (const float*)d_in[20];

    float* out = (float*)d_out;

    int*   knn;  cudaGetSymbolAddress((void**)&knn,  g_knn);
    float* d2;   cudaGetSymbolAddress((void**)&d2,   g_d2);
    float* Ab;   cudaGetSymbolAddress((void**)&Ab,   g_A);
    float* H;    cudaGetSymbolAddress((void**)&H,    g_H);
    float* T;    cudaGetSymbolAddress((void**)&T,    g_T);
    float* x1;   cudaGetSymbolAddress((void**)&x1,   g_x1);
    float* x2;   cudaGetSymbolAddress((void**)&x2,   g_x2);
    float* xcat; cudaGetSymbolAddress((void**)&xcat, g_xcat);
    float* sf;   cudaGetSymbolAddress((void**)&sf,   g_sf);
    float* hg;   cudaGetSymbolAddress((void**)&hg,   g_hg);
    __nv_bfloat16 *Acat, *Wcat;
    cudaGetSymbolAddress((void**)&Acat, g_Acat);
    cudaGetSymbolAddress((void**)&Wcat, g_Wcat);

    const int ROWS = BATCH*NPTS*KNN;   // 16000
    const int PTS  = BATCH*NPTS;       // 2000

    // ======== weight prep (independent of data path — issued first) ========
    split_w3_kernel<<<dim3(512/32, 256/32), 256>>>(c3_w2, Wcat);

    // ======== EdgeConv 1 (fully fused): pos -> x1 (32) ========
    run_knn<3>(pos, d2, knn);
    ec1_fused_kernel<<<250, 256>>>(pos, knn, c1_w1, c1_b1, c1_w2, c1_b2, x1, xcat);

    // ======== EdgeConv 2: x1 (32) -> x2 (128) ========
    run_knn<32>(x1, d2, knn);
    run_sgemm64_dual(x1, c2_w1, c2_w1 + 32*64, nullptr, Ab, PTS, 64, 32);
    edge_combine_kernel<<<(ROWS*16 + 255)/256, 256>>>(Ab, Ab + 64, 32, knn, c2_b1, H, 16);
    {
        dim3 grid(1, 125);
        c2b_fused_kernel<<<grid, 256>>>(H, c2_w2, c2_b2, x2, xcat);
    }

    // ======== EdgeConv 3: x2 (128) -> x3 (512) ========
    run_knn<128>(x2, d2, knn);
    run_sgemm64_dual(x2, c3_w1, c3_w1 + 128*256, nullptr, T, PTS, 256, 128);
    edge_combine_split_kernel<<<(ROWS*64 + 255)/256, 256>>>(T, T + 256, 128, knn, c3_b1, Acat);
    c3b_mma_fused_kernel<<<dim3(125, 4), 256>>>(Acat, Wcat, c3_b2, xcat);

    // ======== shared MLP: xcat[2000,672] -> 256 (relu) -> sf[2000,128] ========
    run_sgemm64(xcat, sm_w1, sm_b1, H,  PTS, 256, 672, 1);
    run_sgemm64(H,    sm_w2, sm_b2, sf, PTS, 128, 256, 0);

    // ======== global pool + hg (fused) + hh dual-GEMM ========
    gpool_hg_kernel<<<BATCH, 1024>>>(sf, ec_w1 + 256*128, ec_b1, hg);
    run_sgemm64_dual(sf, ec_w1, ec_w1 + 128*128, nullptr, Ab, PTS, 128, 128);

    // ======== all-pairs classifier ========
    {
        dim3 grid((NPTS + 127)/128, (NPTS + 127)/128, BATCH);
        pair_kernel<<<grid, 256>>>(Ab, hg, ec_w2, ec_b2, out);
    }
}